// round 6
// baseline (speedup 1.0000x reference)
#include <cuda_runtime.h>
#include <math.h>

#define T_ 128
#define N_ 256
#define L_ 256
#define H_ 256
#define COND_ 64
#define ROWS_ (T_ * N_)   // 32768
#define OUTW_ 770         // 1 + 1 + H + L + L

typedef unsigned long long u64;

// ---------------- scratch (single __device__ symbol, no allocations) -------
// XIN (ROWS*320) is reused as HD (T*N*256) after phase A.
#define XIN_OFF 0L
#define XA_OFF  (XIN_OFF + (long)ROWS_ * 320)
#define XB_OFF  (XA_OFF  + (long)ROWS_ * 256)
#define GI_OFF  (XB_OFF  + (long)ROWS_ * 256)
#define KB_OFF  (GI_OFF  + (long)ROWS_ * 768)
#define WB_OFF  (KB_OFF  + (long)ROWS_ * 256)
#define CC_OFF  (WB_OFF  + (long)ROWS_ * 256)
#define SCRATCH_FLOATS (CC_OFF + (long)ROWS_)

__device__ float g_scratch[SCRATCH_FLOATS];
// one epoch flag per GRU block, 128B apart
__device__ unsigned g_flag[128 * 32];

// ---------------- packed fp32x2 helpers (sm_103a) ---------------------------
#define FMA2(d, a, b) \
    asm("fma.rn.f32x2 %0, %1, %2, %0;" : "+l"(d) : "l"(a), "l"(b))
#define DUP2(d, x) \
    asm("mov.b64 %0, {%1, %1};" : "=l"(d) : "f"(x))
#define UNPACK2(lo, hi, v) \
    asm("mov.b64 {%0, %1}, %2;" : "=f"(lo), "=f"(hi) : "l"(v))

#define CPASYNC16(saddr, gptr) \
    asm volatile("cp.async.ca.shared.global [%0], [%1], 16;" \
                 :: "r"(saddr), "l"(gptr))
#define CPASYNC_COMMIT() asm volatile("cp.async.commit_group;" ::: "memory")
#define CPASYNC_WAIT0()  asm volatile("cp.async.wait_group 0;" ::: "memory")

// ---------------------------------------------------------------------------
__global__ __launch_bounds__(256) void t0_kernel(
    const float* __restrict__ p0, const float* __restrict__ M,
    const float* __restrict__ C, float* __restrict__ XIN, float* __restrict__ CC)
{
    int n = blockIdx.x;
    int tid = threadIdx.x;
    float v = p0[(long)n * L_ + tid];
    int any = __syncthreads_or(v != 0.f);
    if (!any) {
        XIN[(long)n * 320 + 64 + tid] = M[(long)n * L_ * H_ + tid];
        if (tid == 0) CC[n] = C[(long)n * L_];
        return;
    }
    __shared__ float red[256];
    __shared__ float ps[256];
    ps[tid] = v;
    __syncthreads();
    float acc = 0.f;
    const float* Mn = M + (long)n * L_ * H_;
    for (int l = 0; l < L_; l++)
        acc = fmaf(ps[l], Mn[(long)l * H_ + tid], acc);
    XIN[(long)n * 320 + 64 + tid] = acc;
    red[tid] = ps[tid] * C[(long)n * L_ + tid];
    __syncthreads();
    for (int s = 128; s > 0; s >>= 1) {
        if (tid < s) red[tid] += red[tid + s];
        __syncthreads();
    }
    if (tid == 0) CC[n] = red[0];
}

// ---------------------------------------------------------------------------
__global__ __launch_bounds__(256) void gather_kernel(
    const float* __restrict__ cond, const float* __restrict__ M,
    const float* __restrict__ C, const int* __restrict__ actions,
    float* __restrict__ XIN, float* __restrict__ CC)
{
    int r = threadIdx.x >> 5, lane = threadIdx.x & 31;
    long idx = (long)blockIdx.x * 8 + r;    // t*N + n
    int t = (int)(idx / N_), n = (int)(idx % N_);
    float4* dst = (float4*)(XIN + idx * 320);
    const float4* csrc = (const float4*)(cond + idx * COND_);
    if (lane < 16) dst[lane] = csrc[lane];
    if (t > 0) {
        int a = actions[idx - N_];          // actions[t-1, n]
        const float4* msrc = (const float4*)(M + ((long)n * L_ + a) * H_);
#pragma unroll
        for (int i = 0; i < 2; i++) dst[16 + lane + i * 32] = msrc[lane + i * 32];
        if (lane == 0) CC[idx] = C[(long)n * L_ + a];
    }
}

// ---------------------------------------------------------------------------
// fp32 GEMM: 128x64 tile, 8x4/thread (row-pair f32x2 accs), frag-pipelined.
template <bool TRANSB, bool RELU>
__global__ __launch_bounds__(256, 2) void gemm_kernel(
    const float* __restrict__ A, const float* __restrict__ B,
    const float* __restrict__ bias, float* __restrict__ C,
    int M, int N, int K, int lda, int ldb, int ldc,
    long batchA, long batchB, long batchC)
{
    constexpr int BM = 128, BN = 64, BK = 16;
    __shared__ float As[2][BK][BM + 4];
    __shared__ float Bs[2][BK][BN + 4];

    long bz = blockIdx.z;
    A += bz * batchA; B += bz * batchB; C += bz * batchC;
    int m0 = blockIdx.x * BM, n0 = blockIdx.y * BN;
    int tid = threadIdx.x;
    int tx = tid & 15, ty = tid >> 4;

    int am[2], ac[2];
#pragma unroll
    for (int i = 0; i < 2; i++) {
        int idx = tid + i * 256;
        am[i] = idx & 127; ac[i] = idx >> 7;
    }
    int bk = tid >> 4, bn4 = tid & 15;
    int bn = tid & 63, bc2 = tid >> 6;

    u64 acc[4][4];
#pragma unroll
    for (int p = 0; p < 4; p++)
#pragma unroll
        for (int c = 0; c < 4; c++) acc[p][c] = 0ull;

    {
#pragma unroll
        for (int i = 0; i < 2; i++) {
            float4 v = *(const float4*)&A[(long)(m0 + am[i]) * lda + ac[i] * 4];
            As[0][ac[i] * 4 + 0][am[i]] = v.x;
            As[0][ac[i] * 4 + 1][am[i]] = v.y;
            As[0][ac[i] * 4 + 2][am[i]] = v.z;
            As[0][ac[i] * 4 + 3][am[i]] = v.w;
        }
        if (!TRANSB) {
            float4 b = *(const float4*)&B[(long)bk * ldb + n0 + bn4 * 4];
            *(float4*)&Bs[0][bk][bn4 * 4] = b;
        } else {
            float4 b = *(const float4*)&B[(long)(n0 + bn) * ldb + bc2 * 4];
            Bs[0][bc2 * 4 + 0][bn] = b.x;
            Bs[0][bc2 * 4 + 1][bn] = b.y;
            Bs[0][bc2 * 4 + 2][bn] = b.z;
            Bs[0][bc2 * 4 + 3][bn] = b.w;
        }
    }
    __syncthreads();

    int nk = K / BK;
    float4 ra[2], rb;
    for (int it = 0; it < nk; it++) {
        int buf = it & 1;
        bool has_next = (it + 1 < nk);
        if (has_next) {
            int k0 = (it + 1) * BK;
#pragma unroll
            for (int i = 0; i < 2; i++)
                ra[i] = *(const float4*)&A[(long)(m0 + am[i]) * lda + k0 + ac[i] * 4];
            if (!TRANSB)
                rb = *(const float4*)&B[(long)(k0 + bk) * ldb + n0 + bn4 * 4];
            else
                rb = *(const float4*)&B[(long)(n0 + bn) * ldb + k0 + bc2 * 4];
        }
        ulonglong2 a01c = *(const ulonglong2*)&As[buf][0][ty * 8];
        ulonglong2 a23c = *(const ulonglong2*)&As[buf][0][ty * 8 + 4];
        float4 bfc = *(const float4*)&Bs[buf][0][tx * 4];
#pragma unroll
        for (int k = 0; k < BK; k++) {
            ulonglong2 a01n, a23n; float4 bfn;
            if (k < BK - 1) {
                a01n = *(const ulonglong2*)&As[buf][k + 1][ty * 8];
                a23n = *(const ulonglong2*)&As[buf][k + 1][ty * 8 + 4];
                bfn = *(const float4*)&Bs[buf][k + 1][tx * 4];
            }
            u64 bd0, bd1, bd2, bd3;
            DUP2(bd0, bfc.x); DUP2(bd1, bfc.y); DUP2(bd2, bfc.z); DUP2(bd3, bfc.w);
            FMA2(acc[0][0], a01c.x, bd0); FMA2(acc[0][1], a01c.x, bd1);
            FMA2(acc[0][2], a01c.x, bd2); FMA2(acc[0][3], a01c.x, bd3);
            FMA2(acc[1][0], a01c.y, bd0); FMA2(acc[1][1], a01c.y, bd1);
            FMA2(acc[1][2], a01c.y, bd2); FMA2(acc[1][3], a01c.y, bd3);
            FMA2(acc[2][0], a23c.x, bd0); FMA2(acc[2][1], a23c.x, bd1);
            FMA2(acc[2][2], a23c.x, bd2); FMA2(acc[2][3], a23c.x, bd3);
            FMA2(acc[3][0], a23c.y, bd0); FMA2(acc[3][1], a23c.y, bd1);
            FMA2(acc[3][2], a23c.y, bd2); FMA2(acc[3][3], a23c.y, bd3);
            if (k < BK - 1) { a01c = a01n; a23c = a23n; bfc = bfn; }
        }
        if (has_next) {
            int nb = buf ^ 1;
#pragma unroll
            for (int i = 0; i < 2; i++) {
                As[nb][ac[i] * 4 + 0][am[i]] = ra[i].x;
                As[nb][ac[i] * 4 + 1][am[i]] = ra[i].y;
                As[nb][ac[i] * 4 + 2][am[i]] = ra[i].z;
                As[nb][ac[i] * 4 + 3][am[i]] = ra[i].w;
            }
            if (!TRANSB) {
                *(float4*)&Bs[nb][bk][bn4 * 4] = rb;
            } else {
                Bs[nb][bc2 * 4 + 0][bn] = rb.x;
                Bs[nb][bc2 * 4 + 1][bn] = rb.y;
                Bs[nb][bc2 * 4 + 2][bn] = rb.z;
                Bs[nb][bc2 * 4 + 3][bn] = rb.w;
            }
        }
        __syncthreads();
    }

    float4 bv = make_float4(0.f, 0.f, 0.f, 0.f);
    if (bias) bv = *(const float4*)&bias[n0 + tx * 4];
#pragma unroll
    for (int p = 0; p < 4; p++) {
        float r0[4], r1[4];
#pragma unroll
        for (int c = 0; c < 4; c++) UNPACK2(r0[c], r1[c], acc[p][c]);
        r0[0] += bv.x; r0[1] += bv.y; r0[2] += bv.z; r0[3] += bv.w;
        r1[0] += bv.x; r1[1] += bv.y; r1[2] += bv.z; r1[3] += bv.w;
        if (RELU) {
#pragma unroll
            for (int c = 0; c < 4; c++) {
                r0[c] = fmaxf(r0[c], 0.f);
                r1[c] = fmaxf(r1[c], 0.f);
            }
        }
        int m = m0 + ty * 8 + 2 * p;
        *(float4*)&C[(long)m * ldc + n0 + tx * 4] = *(float4*)r0;
        *(float4*)&C[(long)(m + 1) * ldc + n0 + tx * 4] = *(float4*)r1;
    }
}

// ---------------------------------------------------------------------------
// persistent GRU v4: per-producer epoch flags + cp.async chunk exchange.
// 128 blocks (16 jt x 8 nt). Block (jt,nt) computes j in [jt*16, jt*16+16)
// for n in [nt*32, nt*32+32). Only the 15 same-nt peers' j-slices (2KB each)
// are streamed in per step; own slice stays in smem.
#define GRU_BLOCKS 128
#define HSTR 260
#define W4_BYTES  (64 * 48 * 16)            // 49152
#define HS_BYTES  (32 * HSTR * 4)           // 33280
#define RED_OFF_B (W4_BYTES + HS_BYTES)     // 82432
#define GRU_SMEM  (RED_OFF_B + 128 * 12 * 8)

__device__ __forceinline__ float sigmf(float x) { return 1.f / (1.f + __expf(-x)); }
__device__ __forceinline__ float tanhfast(float x) { return 2.f / (1.f + __expf(-2.f * x)) - 1.f; }

__global__ __launch_bounds__(256) void gru_persistent(
    const float* __restrict__ GI, const float* __restrict__ h0,
    const float* __restrict__ W_hh, const float* __restrict__ b_hh,
    float* __restrict__ HD)
{
    extern __shared__ float smem[];
    float4* w4 = (float4*)smem;                       // [64 chunks][48 rows]
    float* hs = smem + W4_BYTES / 4;                  // [32][HSTR]
    u64* redm = (u64*)(smem + RED_OFF_B / 4);         // [128][12]
    unsigned hs_saddr;
    {
        unsigned sb;
        asm("{ .reg .u64 t; cvta.to.shared.u64 t, %1; cvt.u32.u64 %0, t; }"
            : "=r"(sb) : "l"(smem));
        hs_saddr = sb + W4_BYTES;
    }

    int tid = threadIdx.x;
    int jt = blockIdx.x & 15, nt = blockIdx.x >> 4;
    int j0 = jt * 16, n0 = nt * 32;
    int kg = tid >> 7;
    int lt = tid & 127;
    int jj = lt & 15, nn8 = lt >> 4;
    int j = j0 + jj;

    unsigned* myflag = &g_flag[(nt * 16 + jt) * 32];
    unsigned* srcflag = (tid < 15)
        ? &g_flag[(nt * 16 + ((jt + 1 + tid) & 15)) * 32] : nullptr;

    // W slice -> smem
    for (int e = tid; e < 48 * 64; e += 256) {
        int c = e & 63, r = e >> 6;
        int g = r >> 4, jr = r & 15;
        w4[c * 48 + r] = *(const float4*)&W_hh[(long)(g * 256 + j0 + jr) * 256 + c * 4];
    }
    float bhr = b_hh[j], bhz = b_hh[256 + j], bhn = b_hh[512 + j];

    float gi_r[4], gi_z[4], gi_n[4];
    if (kg == 0) {
#pragma unroll
        for (int i = 0; i < 4; i++) {
            const float* g = GI + ((long)(n0 + nn8 + 8 * i)) * 768;
            gi_r[i] = g[j]; gi_z[i] = g[256 + j]; gi_n[i] = g[512 + j];
        }
    }
    int cbase = kg * 32;

    for (int t = 0; t < T_; t++) {
        if (t == 0) {
            // full h0 tile
            int n = tid >> 3, f = tid & 7;
            const float4* src = (const float4*)(h0 + (long)(n0 + n) * H_);
            float4* dst = (float4*)(hs + n * HSTR);
#pragma unroll
            for (int i = 0; i < 8; i++) dst[f + 8 * i] = src[f + 8 * i];
            __syncthreads();
        } else {
            // wait for the 15 peer slices of h(t-1)
            if (tid < 15) {
                unsigned v;
                do {
                    asm volatile("ld.acquire.gpu.global.u32 %0, [%1];"
                                 : "=r"(v) : "l"(srcflag) : "memory");
                } while (v < (unsigned)t);
            }
            __syncthreads();   // bar A
            // stream 15 x 2KB chunks into hs
            const float* hprev = HD + (long)(t - 1) * N_ * H_;
            for (int e = tid; e < 1920; e += 256) {
                int m = e >> 7;                      // 0..14
                int src = (jt + 1 + m) & 15;
                int row = (e >> 2) & 31;
                int q = e & 3;
                const float* g = hprev + (long)(n0 + row) * H_ + src * 16 + q * 4;
                CPASYNC16(hs_saddr + row * (HSTR * 4) + src * 64 + q * 16, g);
            }
            CPASYNC_COMMIT();
            CPASYNC_WAIT0();
            __syncthreads();   // bar B
        }

        u64 acc[4][3];
#pragma unroll
        for (int i = 0; i < 4; i++)
#pragma unroll
            for (int g = 0; g < 3; g++) acc[i][g] = 0ull;

#pragma unroll 8
        for (int c = cbase; c < cbase + 32; c++) {
            const ulonglong2* wrow = (const ulonglong2*)(w4 + c * 48);
            ulonglong2 w0 = wrow[jj];
            ulonglong2 w1 = wrow[16 + jj];
            ulonglong2 w2 = wrow[32 + jj];
#pragma unroll
            for (int i = 0; i < 4; i++) {
                ulonglong2 hv = *(const ulonglong2*)(hs + (nn8 + 8 * i) * HSTR + c * 4);
                FMA2(acc[i][0], hv.x, w0.x); FMA2(acc[i][0], hv.y, w0.y);
                FMA2(acc[i][1], hv.x, w1.x); FMA2(acc[i][1], hv.y, w1.y);
                FMA2(acc[i][2], hv.x, w2.x); FMA2(acc[i][2], hv.y, w2.y);
            }
        }

        if (kg == 1) {
#pragma unroll
            for (int i = 0; i < 4; i++)
#pragma unroll
                for (int g = 0; g < 3; g++) redm[lt * 12 + i * 3 + g] = acc[i][g];
        }
        __syncthreads();   // bar C

        if (kg == 0) {
            float* hout = HD + (long)t * N_ * H_;
#pragma unroll
            for (int i = 0; i < 4; i++) {
                float lo, hi, s[3];
#pragma unroll
                for (int g = 0; g < 3; g++) {
                    UNPACK2(lo, hi, acc[i][g]);
                    s[g] = lo + hi;
                    UNPACK2(lo, hi, redm[lt * 12 + i * 3 + g]);
                    s[g] += lo + hi;
                }
                int nl = nn8 + 8 * i;
                float rg = sigmf(gi_r[i] + s[0] + bhr);
                float z  = sigmf(gi_z[i] + s[1] + bhz);
                float nv = tanhfast(gi_n[i] + rg * (s[2] + bhn));
                float hp = hs[nl * HSTR + j];
                float hn = (1.f - z) * nv + z * hp;
                hs[nl * HSTR + j] = hn;                       // own slice in smem
                hout[(long)(n0 + nl) * H_ + j] = hn;          // for peers + epilogue
            }
            if (t < T_ - 1) __threadfence();   // order HD stores before flag
        }
        __syncthreads();   // bar D

        if (t < T_ - 1) {
            if (tid == 0) {
                asm volatile("st.release.gpu.global.u32 [%0], %1;"
                             :: "l"(myflag), "r"((unsigned)(t + 1)) : "memory");
            }
            if (kg == 0) {   // prefetch gi(t+1)
#pragma unroll
                for (int i = 0; i < 4; i++) {
                    const float* g = GI + ((long)(t + 1) * N_ + n0 + nn8 + 8 * i) * 768;
                    gi_r[i] = g[j]; gi_z[i] = g[256 + j]; gi_n[i] = g[512 + j];
                }
            }
        }
    }
}

// ---------------------------------------------------------------------------
// warp-per-(t,n): h copy, softmax(w*cc), one-hot, action, value.
__global__ __launch_bounds__(256) void epilogue_kernel(
    const float* __restrict__ WB, const float* __restrict__ CC,
    const int* __restrict__ actions, const float* __restrict__ Wc,
    const float* __restrict__ bc, const float* __restrict__ HD,
    float* __restrict__ out)
{
    int wid = threadIdx.x >> 5, lane = threadIdx.x & 31;
    long idx = (long)blockIdx.x * 8 + wid;   // t*N + n
    int t = (int)(idx / N_), n = (int)(idx % N_);
    float cc = CC[idx];
    long base = idx * OUTW_;

    const float4* hrow = (const float4*)(HD + idx * 256);
    const float4* wc = (const float4*)Wc;
    float4 h0v = hrow[lane * 2], h1v = hrow[lane * 2 + 1];
    float4 c0 = wc[lane * 2], c1 = wc[lane * 2 + 1];
    float2* hdst = (float2*)(out + base + 2 + lane * 8);
    hdst[0] = make_float2(h0v.x, h0v.y);
    hdst[1] = make_float2(h0v.z, h0v.w);
    hdst[2] = make_float2(h1v.x, h1v.y);
    hdst[3] = make_float2(h1v.z, h1v.w);
    float d = h0v.x * c0.x + h0v.y * c0.y + h0v.z * c0.z + h0v.w * c0.w
            + h1v.x * c1.x + h1v.y * c1.y + h1v.z * c1.z + h1v.w * c1.w;
#pragma unroll
    for (int o = 16; o; o >>= 1) d += __shfl_xor_sync(~0u, d, o);

    const float4* wrow = (const float4*)(WB + ((long)n * T_ + t) * L_);
    float4 w0 = wrow[lane * 2], w1 = wrow[lane * 2 + 1];
    float wv[8] = {w0.x * cc, w0.y * cc, w0.z * cc, w0.w * cc,
                   w1.x * cc, w1.y * cc, w1.z * cc, w1.w * cc};
    float mx = wv[0];
#pragma unroll
    for (int i = 1; i < 8; i++) mx = fmaxf(mx, wv[i]);
#pragma unroll
    for (int o = 16; o; o >>= 1) mx = fmaxf(mx, __shfl_xor_sync(~0u, mx, o));
    float e[8], s = 0.f;
#pragma unroll
    for (int i = 0; i < 8; i++) { e[i] = expf(wv[i] - mx); s += e[i]; }
#pragma unroll
    for (int o = 16; o; o >>= 1) s += __shfl_xor_sync(~0u, s, o);
    float inv = 1.f / s;

    int a = actions[idx];
    float2* pdst = (float2*)(out + base + 258 + lane * 8);
    float2* odst = (float2*)(out + base + 514 + lane * 8);
#pragma unroll
    for (int i = 0; i < 4; i++) {
        pdst[i] = make_float2(e[2 * i] * inv, e[2 * i + 1] * inv);
        int l0 = lane * 8 + 2 * i;
        odst[i] = make_float2(l0 == a ? 1.f : 0.f, l0 + 1 == a ? 1.f : 0.f);
    }
    if (lane == 0) {
        out[base + 0] = (float)a;
        out[base + 1] = d + bc[0];
    }
}

// ---------------------------------------------------------------------------
extern "C" void kernel_launch(void* const* d_in, const int* in_sizes, int n_in,
                              void* d_out, int out_size)
{
    const float* cond = (const float*)d_in[0];
    const float* M    = (const float*)d_in[1];
    const float* Km   = (const float*)d_in[2];
    const float* Cm   = (const float*)d_in[3];
    const float* h0   = (const float*)d_in[4];
    const float* p0   = (const float*)d_in[5];
    const float* W0   = (const float*)d_in[6];
    const float* b0   = (const float*)d_in[7];
    const float* W1   = (const float*)d_in[8];
    const float* b1   = (const float*)d_in[9];
    const float* W2   = (const float*)d_in[10];
    const float* b2   = (const float*)d_in[11];
    const float* W_ih = (const float*)d_in[12];
    const float* W_hh = (const float*)d_in[13];
    const float* b_ih = (const float*)d_in[14];
    const float* b_hh = (const float*)d_in[15];
    const float* Wa   = (const float*)d_in[16];
    const float* ba   = (const float*)d_in[17];
    const float* Wc   = (const float*)d_in[18];
    const float* bc   = (const float*)d_in[19];
    const int* actions = (const int*)d_in[20];
    float* out = (float*)d_out;

    float* base = nullptr;
    cudaGetSymbolAddress((void**)&base, g_scratch);
    float* XIN = base + XIN_OFF;
    float* XA  = base + XA_OFF;
    float* XB  = base + XB_OFF;
    float* GI  = base + GI_OFF;
    float* KB  = base + KB_OFF;
    float* WB  = base + WB_OFF;
    float* CC  = base + CC_OFF;
    float* HD  = base + XIN_OFF;   // reuse XIN region after phase A

    void* flag_addr = nullptr;
    cudaGetSymbolAddress(&flag_addr, g_flag);

    cudaFuncSetAttribute(gru_persistent,
                         cudaFuncAttributeMaxDynamicSharedMemorySize, GRU_SMEM);

    // phase A: inputs -> gi (fully parallel over T*N)
    t0_kernel<<<N_, 256>>>(p0, M, Cm, XIN, CC);
    gather_kernel<<<ROWS_ / 8, 256>>>(cond, M, Cm, actions, XIN, CC);
    gemm_kernel<false, true><<<dim3(ROWS_ / 128, 4, 1), 256>>>(
        XIN, W0, b0, XA, ROWS_, 256, 320, 320, 256, 256, 0, 0, 0);
    gemm_kernel<false, true><<<dim3(ROWS_ / 128, 4, 1), 256>>>(
        XA, W1, b1, XB, ROWS_, 256, 256, 256, 256, 256, 0, 0, 0);
    gemm_kernel<false, true><<<dim3(ROWS_ / 128, 4, 1), 256>>>(
        XB, W2, b2, XA, ROWS_, 256, 256, 256, 256, 256, 0, 0, 0);
    gemm_kernel<true, false><<<dim3(ROWS_ / 128, 12, 1), 256>>>(
        XA, W_ih, b_ih, GI, ROWS_, 768, 256, 256, 256, 768, 0, 0, 0);

    // phase B: persistent GRU (per-producer flags + cp.async exchange)
    cudaMemsetAsync(flag_addr, 0, 128 * 32 * sizeof(unsigned));
    gru_persistent<<<GRU_BLOCKS, 256, GRU_SMEM>>>(GI, h0, W_hh, b_hh, HD);

    // phase C: actor head (parallel again)
    gemm_kernel<false, false><<<dim3(ROWS_ / 128, 4, 1), 256>>>(
        HD, Wa, ba, KB, ROWS_, 256, 256, 256, 256, 256, 0, 0, 0);
    gemm_kernel<true, false><<<dim3(1, 4, N_), 256>>>(
        KB, Km, nullptr, WB, T_, 256, 256, N_ * 256, 256, 256,
        256L, (long)L_ * H_, (long)T_ * L_);
    epilogue_kernel<<<ROWS_ / 8, 256>>>(WB, CC, actions, Wc, bc, HD, out);
}